// round 7
// baseline (speedup 1.0000x reference)
#include <cuda_runtime.h>
#include <math.h>

#define NB   64
#define NN   512
#define NC   128
#define NFS  16
#define NRES 511
#define NBN  (NB*NN)
#define TR   32
#define TROWS (TR + NFS - 1)   // 47 tile rows

// Scratch (no allocations allowed)
__device__ float g_score[NBN];
__device__ float g_ssrc[NBN];
__device__ float g_sdst[NBN];
__device__ int   g_order[NBN];
__device__ float g_sr[NBN];
__device__ float g_dsrc[NBN];
__device__ float g_ddst[NBN];
__device__ float g_wv[NB*NRES];
__device__ int   g_jumps[NB*NRES];
__device__ int   g_cnt1[NB];   // zero-init at load; never reset (mod trick)
__device__ int   g_cnt2[NB];

// ============ K1: scores (wide grid) + per-batch sort in last CTA ============
__global__ void k_scores_sort(const float* __restrict__ x,
                              const float* __restrict__ sw,
                              const float* __restrict__ ap) {
    __shared__ float sp[8][4][8];
    __shared__ float sfin[8][4];
    __shared__ unsigned long long sk[NN];   // sort keys (last CTA only)
    __shared__ int s_last;
    int t = threadIdx.x, w = t >> 5, lane = t & 31;
    int node = blockIdx.x * 8 + w;
    int b = blockIdx.x >> 6;                // 64 CTAs per batch

    float4 xv = *(const float4*)(x  + (size_t)node * NC + lane * 4);
    float4 wv = *(const float4*)(sw + lane * 4);
    float4 as = *(const float4*)(ap + lane * 4);
    float4 ad = *(const float4*)(ap + NC + lane * 4);
    float s  = xv.x*wv.x + xv.y*wv.y + xv.z*wv.z + xv.w*wv.w;
    float ps = xv.x*as.x + xv.y*as.y + xv.z*as.z + xv.w*as.w;
    float pd = xv.x*ad.x + xv.y*ad.y + xv.z*ad.z + xv.w*ad.w;
    float wn = wv.x*wv.x + wv.y*wv.y + wv.z*wv.z + wv.w*wv.w;
    #pragma unroll
    for (int o = 16; o >= 8; o >>= 1) {
        s  += __shfl_xor_sync(0xffffffffu, s,  o);
        ps += __shfl_xor_sync(0xffffffffu, ps, o);
        pd += __shfl_xor_sync(0xffffffffu, pd, o);
        wn += __shfl_xor_sync(0xffffffffu, wn, o);
    }
    if (lane < 8) {
        sp[w][0][lane] = s;  sp[w][1][lane] = ps;
        sp[w][2][lane] = pd; sp[w][3][lane] = wn;
    }
    __syncthreads();
    if (t < 32) {
        int nd = t >> 2, v = t & 3;
        const float* q = sp[nd][v];
        sfin[nd][v] = ((q[0]+q[1])+(q[2]+q[3])) + ((q[4]+q[5])+(q[6]+q[7]));
    }
    __syncthreads();
    if (t < 8) {
        int gn = blockIdx.x * 8 + t;
        g_score[gn] = sfin[t][0] / sqrtf(sfin[t][3]);
        g_ssrc[gn]  = sfin[t][1];
        g_sdst[gn]  = sfin[t][2];
    }

    // --- release + elect last CTA of this batch ---
    __threadfence();
    __syncthreads();
    if (t == 0) {
        int old = atomicAdd(&g_cnt1[b], 1);
        s_last = ((old & 63) == 63);
        __threadfence();
    }
    __syncthreads();
    if (!s_last) return;

    // --- per-batch bitonic sort, 256 threads / 512 keys, SMEM ---
    for (int e = t; e < NN; e += 256) {
        float sv = g_score[b * NN + e];
        unsigned u = __float_as_uint(sv);
        u = (u & 0x80000000u) ? ~u : (u | 0x80000000u);
        u = ~u;                                     // descending score
        sk[e] = ((unsigned long long)u << 32) | (unsigned)e;
    }
    __syncthreads();
    for (int k = 2; k <= NN; k <<= 1) {
        for (int j = k >> 1; j > 0; j >>= 1) {
            int e  = ((t & ~(j - 1)) << 1) | (t & (j - 1));
            int e2 = e | j;
            unsigned long long a = sk[e], c = sk[e2];
            bool asc = ((e & k) == 0);
            if ((a > c) == asc) { sk[e] = c; sk[e2] = a; }
            __syncthreads();
        }
    }
    for (int e = t; e < NN; e += 256) {
        int idx = (int)(sk[e] & 0xffffffffu);
        int gi  = b * NN + idx;
        g_order[b * NN + e] = idx;
        g_sr[b * NN + e]    = tanhf(g_score[gi]);
        g_dsrc[b * NN + e]  = g_ssrc[gi];
        g_ddst[b * NN + e]  = g_sdst[gi];
    }
}

// ======== K2: banded windows (wide grid) + per-batch chain in last CTA =======
__global__ void k_windows_chain(const float* __restrict__ x,
                                const int*   __restrict__ ep,
                                float* __restrict__ out) {
    __shared__ __align__(16) float tile[TROWS * NC];    // 24064 B (reused by chain)
    __shared__ __align__(16) float sp8[TR * 15 * 8];    // 15360 B
    __shared__ __align__(16) float skk[TR * 15];        // 1920 B
    __shared__ __align__(16) float sddst[48];
    __shared__ int s_last, s_count;
    int b  = blockIdx.y;
    int r0 = blockIdx.x * TR;
    int t = threadIdx.x, w = t >> 5, lane = t & 31;
    const int* ord = g_order + b * NN;

    for (int rr = w; rr < TROWS; rr += 8) {
        int gr  = r0 + rr;
        int grc = gr < NN ? gr : (NN - 1);
        int id  = ord[grc];
        float4 v = *(const float4*)(x + ((size_t)(b * NN + id)) * NC + lane * 4);
        *(float4*)(tile + rr * NC + lane * 4) = v;
    }
    if (t < TROWS) {
        int gr  = r0 + t;
        int grc = gr < NN ? gr : (NN - 1);
        sddst[t] = g_ddst[b * NN + grc];
    }
    __syncthreads();

    // Phase A: warp w owns source rows rbase..rbase+3 in registers
    int rbase = w * 4;
    float4 xs0 = *(const float4*)(tile + (rbase + 0) * NC + lane * 4);
    float4 xs1 = *(const float4*)(tile + (rbase + 1) * NC + lane * 4);
    float4 xs2 = *(const float4*)(tile + (rbase + 2) * NC + lane * 4);
    float4 xs3 = *(const float4*)(tile + (rbase + 3) * NC + lane * 4);

    #pragma unroll
    for (int dd = 1; dd <= 18; dd++) {
        float4 xd = *(const float4*)(tile + (rbase + dd) * NC + lane * 4);
        #pragma unroll
        for (int i = 0; i < 4; i++) {
            int j = dd - i;
            if (j >= 1 && j <= 15) {
                float4 xs = (i == 0) ? xs0 : (i == 1) ? xs1 : (i == 2) ? xs2 : xs3;
                float dx = xs.x - xd.x, dy = xs.y - xd.y;
                float dz = xs.z - xd.z, dw = xs.w - xd.w;
                float p = dx*dx + dy*dy + dz*dz + dw*dw;
                p += __shfl_xor_sync(0xffffffffu, p, 16);
                p += __shfl_xor_sync(0xffffffffu, p, 8);
                if (lane < 8)
                    sp8[((rbase + i) * 15 + (j - 1)) * 8 + lane] = p;
            }
        }
    }
    __syncthreads();

    // Phase B1: sum 8 partials, kk = exp(-sqrt(d2)/2) - EPS
    for (int i = t; i < TR * 15; i += 256) {
        int rl = i / 15, jm1 = i - rl * 15;
        bool valid = (r0 + rl + jm1 + 1) < NN;
        float4 a  = *(const float4*)(sp8 + i * 8);
        float4 b4 = *(const float4*)(sp8 + i * 8 + 4);
        float d2 = ((a.x + a.y) + (a.z + a.w)) + ((b4.x + b4.y) + (b4.z + b4.w));
        skk[i] = valid ? (expf(-0.5f * sqrtf(d2)) - 1e-20f) : -1e-20f;
    }
    __syncthreads();

    // Phase B2: thread-per-r softmax / max / argmax
    if (t < TR) {
        int r = r0 + t;
        if (r < NRES) {
            int epoch = *ep;
            float tau = (float)(10.0 * exp((double)epoch * -0.046051701859880914));
            float dsr = g_dsrc[b * NN + r];

            float att[16], kk[16];
            kk[0]  = 1.0f;
            att[0] = dsr + sddst[t];
            #pragma unroll
            for (int j = 1; j < NFS; j++) {
                bool valid = (r + j) < NN;
                kk[j]  = skk[t * 15 + (j - 1)];
                att[j] = valid ? (dsr + sddst[t + j]) : -1e9f;
            }
            float m = att[0];
            #pragma unroll
            for (int j = 1; j < NFS; j++) m = fmaxf(m, att[j]);
            float e[16], ssum = 0.0f;
            #pragma unroll
            for (int j = 0; j < NFS; j++) { e[j] = expf((att[j] - m) / tau); ssum += e[j]; }
            float inv = 1.0f / ssum;

            float wrow = -1e9f, best = -3e9f;
            int bj = 1;
            #pragma unroll
            for (int j = 0; j < NFS; j++) {
                bool valid = (r + j) < NN;
                float q  = kk[j] * (e[j] * inv);
                float qm = valid ? q : -1e9f;
                wrow = fmaxf(wrow, qm);
                if (j >= 1 && qm > best) { best = qm; bj = j; }
            }
            g_wv[b * NRES + r]    = wrow * g_sr[b * NN + r];
            g_jumps[b * NRES + r] = bj;
        }
    }

    // --- release + elect last tile-CTA of this batch ---
    __threadfence();
    __syncthreads();
    if (t == 0) {
        int old = atomicAdd(&g_cnt2[b], 1);
        s_last = ((old & 15) == 15);
        __threadfence();
    }
    __syncthreads();
    if (!s_last) return;

    // --- chain tail: overlay scratch on dead tile buffer ---
    float* swv   = tile;                       // [NRES]
    int*   sj    = (int*)(tile + 512);         // [NRES]
    int*   sord  = (int*)(tile + 1024);        // [NRES]
    int*   spath = (int*)(tile + 1536);        // [NRES]
    float* swt   = tile + 2048;                // [NRES]
    float* part  = tile + 2560;                // [8][NC], 16B-aligned

    for (int i = t; i < NRES; i += 256) {
        swv[i]  = g_wv[b * NRES + i];
        sj[i]   = g_jumps[b * NRES + i];
        sord[i] = g_order[b * NN + i];
    }
    __syncthreads();

    if (t == 0) {     // serial pointer-chase in SMEM
        int p = 0, n = 0;
        while (p < NRES) {
            spath[n] = sord[p];
            swt[n]   = swv[p];
            n++;
            p += sj[p];
        }
        s_count = n;
    }
    __syncthreads();

    int n = s_count;
    const float* xb = x + (size_t)b * NN * NC;
    float ax = 0.f, ay = 0.f, az = 0.f, aw = 0.f;
    #pragma unroll 4
    for (int i = w; i < n; i += 8) {           // 8 warps, warp-strided
        float wt = swt[i];
        float4 xr = *(const float4*)(xb + (size_t)spath[i] * NC + lane * 4);
        ax += wt * xr.x; ay += wt * xr.y; az += wt * xr.z; aw += wt * xr.w;
    }
    part[w * NC + lane * 4 + 0] = ax;
    part[w * NC + lane * 4 + 1] = ay;
    part[w * NC + lane * 4 + 2] = az;
    part[w * NC + lane * 4 + 3] = aw;
    __syncthreads();

    if (t < NC) {
        float sum = 0.0f;
        #pragma unroll
        for (int w2 = 0; w2 < 8; w2++) sum += part[w2 * NC + t];
        out[b * NC + t] = sum;
    }
}

extern "C" void kernel_launch(void* const* d_in, const int* in_sizes, int n_in,
                              void* d_out, int out_size) {
    const float* x   = (const float*)d_in[0];
    // d_in[1] = edge_index (unused by the reference forward pass)
    const float* sw  = (const float*)d_in[2];
    const float* ap  = (const float*)d_in[3];
    const int*   ep  = (const int*)d_in[4];
    float* out = (float*)d_out;

    k_scores_sort<<<NBN / 8, 256>>>(x, sw, ap);
    dim3 gw((NRES + TR - 1) / TR, NB);
    k_windows_chain<<<gw, 256>>>(x, ep, out);
}

// round 8
// speedup vs baseline: 1.3943x; 1.3943x over previous
#include <cuda_runtime.h>
#include <math.h>

#define NB   64
#define NN   512
#define NC   128
#define NFS  16
#define NRES 511
#define NBN  (NB*NN)
#define TR   32
#define TROWS (TR + NFS - 1)   // 47 tile rows

// Scratch (no allocations allowed)
__device__ float g_score[NBN];
__device__ float g_ssrc[NBN];
__device__ float g_sdst[NBN];
__device__ int   g_order[NBN];
__device__ float g_sr[NBN];
__device__ float g_dsrc[NBN];
__device__ float g_ddst[NBN];
__device__ float g_wv[NB*NRES];
__device__ int   g_jumps[NB*NRES];

// -------- Kernel 1: per-node score + attention dots --------
__global__ void k_scores(const float* __restrict__ x,
                         const float* __restrict__ sw,
                         const float* __restrict__ ap) {
    __shared__ float sp[8][4][8];
    __shared__ float sfin[8][4];
    int t = threadIdx.x, w = t >> 5, lane = t & 31;
    int node = blockIdx.x * 8 + w;

    float4 xv = *(const float4*)(x  + (size_t)node * NC + lane * 4);
    float4 wv = *(const float4*)(sw + lane * 4);
    float4 as = *(const float4*)(ap + lane * 4);
    float4 ad = *(const float4*)(ap + NC + lane * 4);
    float s  = xv.x*wv.x + xv.y*wv.y + xv.z*wv.z + xv.w*wv.w;
    float ps = xv.x*as.x + xv.y*as.y + xv.z*as.z + xv.w*as.w;
    float pd = xv.x*ad.x + xv.y*ad.y + xv.z*ad.z + xv.w*ad.w;
    float wn = wv.x*wv.x + wv.y*wv.y + wv.z*wv.z + wv.w*wv.w;
    #pragma unroll
    for (int o = 16; o >= 8; o >>= 1) {
        s  += __shfl_xor_sync(0xffffffffu, s,  o);
        ps += __shfl_xor_sync(0xffffffffu, ps, o);
        pd += __shfl_xor_sync(0xffffffffu, pd, o);
        wn += __shfl_xor_sync(0xffffffffu, wn, o);
    }
    if (lane < 8) {
        sp[w][0][lane] = s;  sp[w][1][lane] = ps;
        sp[w][2][lane] = pd; sp[w][3][lane] = wn;
    }
    __syncthreads();
    if (t < 32) {
        int nd = t >> 2, v = t & 3;
        const float* q = sp[nd][v];
        sfin[nd][v] = ((q[0]+q[1])+(q[2]+q[3])) + ((q[4]+q[5])+(q[6]+q[7]));
    }
    __syncthreads();
    if (t < 8) {
        int gn = blockIdx.x * 8 + t;
        g_score[gn] = sfin[t][0] / sqrtf(sfin[t][3]);
        g_ssrc[gn]  = sfin[t][1];
        g_sdst[gn]  = sfin[t][2];
    }
}

// -------- Kernel 2: register-resident bitonic sort with u64 keys --------
__global__ void k_sort() {
    __shared__ unsigned long long sk[NN];
    int b = blockIdx.x, t = threadIdx.x;
    float sval = g_score[b * NN + t];
    unsigned u = __float_as_uint(sval);
    u = (u & 0x80000000u) ? ~u : (u | 0x80000000u);
    u = ~u;
    unsigned long long key = ((unsigned long long)u << 32) | (unsigned)t;

    #pragma unroll
    for (int k = 2; k <= NN; k <<= 1) {
        #pragma unroll
        for (int j = k >> 1; j > 0; j >>= 1) {
            unsigned long long other;
            if (j >= 32) {
                __syncthreads();
                sk[t] = key;
                __syncthreads();
                other = sk[t ^ j];
            } else {
                other = __shfl_xor_sync(0xffffffffu, key, j);
            }
            bool takeMin = (((t & j) == 0) == ((t & k) == 0));
            bool less = key < other;
            key = (takeMin == less) ? key : other;
        }
    }

    int idx = (int)(key & 0xffffffffu);
    int gi  = b * NN + idx;
    g_order[b * NN + t] = idx;
    g_sr[b * NN + t]    = tanhf(g_score[gi]);
    g_dsrc[b * NN + t]  = g_ssrc[gi];
    g_ddst[b * NN + t]  = g_sdst[gi];
}

// -------- Kernel 3: banded window, register-xs / streamed-xd --------
__global__ void k_windows(const float* __restrict__ x,
                          const int*   __restrict__ ep) {
    __shared__ __align__(16) float tile[TROWS * NC];    // 24064 B
    __shared__ __align__(16) float sp4[TR * 15 * 4];    // 7680 B
    __shared__ __align__(16) float skk[TR * 15];        // 1920 B
    __shared__ __align__(16) float sddst[48];
    int b  = blockIdx.y;
    int r0 = blockIdx.x * TR;
    int t = threadIdx.x, w = t >> 5, lane = t & 31;
    const int* ord = g_order + b * NN;

    for (int rr = w; rr < TROWS; rr += 8) {
        int gr  = r0 + rr;
        int grc = gr < NN ? gr : (NN - 1);
        int id  = ord[grc];
        float4 v = *(const float4*)(x + ((size_t)(b * NN + id)) * NC + lane * 4);
        *(float4*)(tile + rr * NC + lane * 4) = v;
    }
    if (t < TROWS) {
        int gr  = r0 + t;
        int grc = gr < NN ? gr : (NN - 1);
        sddst[t] = g_ddst[b * NN + grc];
    }
    __syncthreads();

    // Phase A: warp w owns source rows rbase..rbase+3 in registers;
    // each dest row read from SMEM exactly once.
    int rbase = w * 4;
    float4 xs0 = *(const float4*)(tile + (rbase + 0) * NC + lane * 4);
    float4 xs1 = *(const float4*)(tile + (rbase + 1) * NC + lane * 4);
    float4 xs2 = *(const float4*)(tile + (rbase + 2) * NC + lane * 4);
    float4 xs3 = *(const float4*)(tile + (rbase + 3) * NC + lane * 4);

    #pragma unroll
    for (int dd = 1; dd <= 18; dd++) {
        float4 xd = *(const float4*)(tile + (rbase + dd) * NC + lane * 4);
        #pragma unroll
        for (int i = 0; i < 4; i++) {
            int j = dd - i;
            if (j >= 1 && j <= 15) {
                float4 xs = (i == 0) ? xs0 : (i == 1) ? xs1 : (i == 2) ? xs2 : xs3;
                float dx = xs.x - xd.x, dy = xs.y - xd.y;
                float dz = xs.z - xd.z, dw = xs.w - xd.w;
                float p = dx*dx + dy*dy + dz*dz + dw*dw;
                p += __shfl_xor_sync(0xffffffffu, p, 16);
                p += __shfl_xor_sync(0xffffffffu, p, 8);
                p += __shfl_xor_sync(0xffffffffu, p, 4);
                if (lane < 4)
                    sp4[((rbase + i) * 15 + (j - 1)) * 4 + lane] = p;
            }
        }
    }
    __syncthreads();

    // Phase B1: sum 4 partials, kk = exp(-sqrt(d2)/2) - EPS
    for (int i = t; i < TR * 15; i += 256) {
        int rl = i / 15, jm1 = i - rl * 15;
        bool valid = (r0 + rl + jm1 + 1) < NN;
        float4 a = *(const float4*)(sp4 + i * 4);
        float d2 = (a.x + a.y) + (a.z + a.w);
        skk[i] = valid ? (expf(-0.5f * sqrtf(d2)) - 1e-20f) : -1e-20f;
    }
    __syncthreads();

    // Phase B2: thread-per-r softmax / max / argmax
    if (t < TR) {
        int r = r0 + t;
        if (r < NRES) {
            int epoch = *ep;
            float tau = (float)(10.0 * exp((double)epoch * -0.046051701859880914));
            float dsr = g_dsrc[b * NN + r];

            float att[16], kk[16];
            kk[0]  = 1.0f;
            att[0] = dsr + sddst[t];
            #pragma unroll
            for (int j = 1; j < NFS; j++) {
                bool valid = (r + j) < NN;
                kk[j]  = skk[t * 15 + (j - 1)];
                att[j] = valid ? (dsr + sddst[t + j]) : -1e9f;
            }
            float m = att[0];
            #pragma unroll
            for (int j = 1; j < NFS; j++) m = fmaxf(m, att[j]);
            float e[16], ssum = 0.0f;
            #pragma unroll
            for (int j = 0; j < NFS; j++) { e[j] = expf((att[j] - m) / tau); ssum += e[j]; }
            float inv = 1.0f / ssum;

            float wrow = -1e9f, best = -3e9f;
            int bj = 1;
            #pragma unroll
            for (int j = 0; j < NFS; j++) {
                bool valid = (r + j) < NN;
                float q  = kk[j] * (e[j] * inv);
                float qm = valid ? q : -1e9f;
                wrow = fmaxf(wrow, qm);
                if (j >= 1 && qm > best) { best = qm; bj = j; }
            }
            g_wv[b * NRES + r]    = wrow * g_sr[b * NN + r];
            g_jumps[b * NRES + r] = bj;
        }
    }
}

// -------- Kernel 4: segment-shortcut parallel chase + masked gather --------
__global__ void k_chain(const float* __restrict__ x, float* __restrict__ out) {
    __shared__ float swv[NRES];
    __shared__ int   sj[NRES];
    __shared__ int   sord[NRES];
    __shared__ int   sexit[NN];       // exit point from each start position
    __shared__ int   sentry[16];      // actual entry point per 32-segment
    __shared__ unsigned smask[16];    // visited bitmask per segment
    __shared__ __align__(16) float part[16][NC];
    int b = blockIdx.x, t = threadIdx.x, w = t >> 5, lane = t & 31;  // 512 thr

    if (t < NRES) {
        swv[t]  = g_wv[b * NRES + t];
        sj[t]   = g_jumps[b * NRES + t];
        sord[t] = g_order[b * NN + t];
    }
    if (t < 16) { sentry[t] = -1; smask[t] = 0u; }
    __syncthreads();

    // Phase 1 (parallel): within-segment exit from every start position
    {
        int p = t;
        int segend = ((t >> 5) + 1) << 5;
        while (p < segend && p < NRES) p += sj[p];
        sexit[t] = p;
    }
    __syncthreads();

    // Phase 2 (t0): hop segment to segment (<=16 dependent LDS)
    if (t == 0) {
        int p = 0;
        while (p < NRES) {
            sentry[p >> 5] = p;
            p = sexit[p];
        }
    }
    __syncthreads();

    // Phase 3 (16 threads): mark visited entries within entered segments
    if (t < 16) {
        int e = sentry[t];
        if (e >= 0) {
            unsigned m = 0u;
            int p = e, segend = (t + 1) << 5;
            while (p < segend && p < NRES) { m |= 1u << (p & 31); p += sj[p]; }
            smask[t] = m;
        }
    }
    __syncthreads();

    // Phase 4: masked dense gather, 16 warps x float4 lanes
    const float* xb = x + (size_t)b * NN * NC;
    float ax = 0.f, ay = 0.f, az = 0.f, aw = 0.f;
    for (int i = w; i < NRES; i += 16) {
        if (smask[i >> 5] & (1u << (i & 31))) {
            float wt = swv[i];
            float4 xr = *(const float4*)(xb + (size_t)sord[i] * NC + lane * 4);
            ax += wt * xr.x; ay += wt * xr.y; az += wt * xr.z; aw += wt * xr.w;
        }
    }
    part[w][lane * 4 + 0] = ax;
    part[w][lane * 4 + 1] = ay;
    part[w][lane * 4 + 2] = az;
    part[w][lane * 4 + 3] = aw;
    __syncthreads();

    if (t < NC) {
        float s = 0.0f;
        #pragma unroll
        for (int w2 = 0; w2 < 16; w2++) s += part[w2][t];
        out[b * NC + t] = s;
    }
}

extern "C" void kernel_launch(void* const* d_in, const int* in_sizes, int n_in,
                              void* d_out, int out_size) {
    const float* x   = (const float*)d_in[0];
    // d_in[1] = edge_index (unused by the reference forward pass)
    const float* sw  = (const float*)d_in[2];
    const float* ap  = (const float*)d_in[3];
    const int*   ep  = (const int*)d_in[4];
    float* out = (float*)d_out;

    k_scores<<<NBN / 8, 256>>>(x, sw, ap);
    k_sort<<<NB, NN>>>();
    dim3 gw((NRES + TR - 1) / TR, NB);
    k_windows<<<gw, 256>>>(x, ep);
    k_chain<<<NB, 512>>>(x, out);
}

// round 9
// speedup vs baseline: 1.4667x; 1.0519x over previous
#include <cuda_runtime.h>
#include <math.h>

#define NB   64
#define NN   512
#define NC   128
#define NFS  16
#define NRES 511
#define NBN  (NB*NN)
#define TR   32
#define TROWS (TR + NFS - 1)   // 47 tile rows

// Scratch (no allocations allowed)
__device__ float g_score[NBN];
__device__ float g_ssrc[NBN];
__device__ float g_sdst[NBN];
__device__ int   g_order[NBN];
__device__ float g_sr[NBN];
__device__ float g_dsrc[NBN];
__device__ float g_ddst[NBN];
__device__ float g_wv[NB*NRES];
__device__ int   g_exit[NBN];        // exit position from every start p
__device__ unsigned g_maskf[NBN];    // visited-bits within segment from p

// -------- Kernel 1: per-node score + attention dots --------
__global__ void k_scores(const float* __restrict__ x,
                         const float* __restrict__ sw,
                         const float* __restrict__ ap) {
    __shared__ float sp[8][4][8];
    __shared__ float sfin[8][4];
    int t = threadIdx.x, w = t >> 5, lane = t & 31;
    int node = blockIdx.x * 8 + w;

    float4 xv = *(const float4*)(x  + (size_t)node * NC + lane * 4);
    float4 wv = *(const float4*)(sw + lane * 4);
    float4 as = *(const float4*)(ap + lane * 4);
    float4 ad = *(const float4*)(ap + NC + lane * 4);
    float s  = xv.x*wv.x + xv.y*wv.y + xv.z*wv.z + xv.w*wv.w;
    float ps = xv.x*as.x + xv.y*as.y + xv.z*as.z + xv.w*as.w;
    float pd = xv.x*ad.x + xv.y*ad.y + xv.z*ad.z + xv.w*ad.w;
    float wn = wv.x*wv.x + wv.y*wv.y + wv.z*wv.z + wv.w*wv.w;
    #pragma unroll
    for (int o = 16; o >= 8; o >>= 1) {
        s  += __shfl_xor_sync(0xffffffffu, s,  o);
        ps += __shfl_xor_sync(0xffffffffu, ps, o);
        pd += __shfl_xor_sync(0xffffffffu, pd, o);
        wn += __shfl_xor_sync(0xffffffffu, wn, o);
    }
    if (lane < 8) {
        sp[w][0][lane] = s;  sp[w][1][lane] = ps;
        sp[w][2][lane] = pd; sp[w][3][lane] = wn;
    }
    __syncthreads();
    if (t < 32) {
        int nd = t >> 2, v = t & 3;
        const float* q = sp[nd][v];
        sfin[nd][v] = ((q[0]+q[1])+(q[2]+q[3])) + ((q[4]+q[5])+(q[6]+q[7]));
    }
    __syncthreads();
    if (t < 8) {
        int gn = blockIdx.x * 8 + t;
        g_score[gn] = sfin[t][0] / sqrtf(sfin[t][3]);
        g_ssrc[gn]  = sfin[t][1];
        g_sdst[gn]  = sfin[t][2];
    }
}

// -------- Kernel 2: register-resident bitonic sort with u64 keys --------
__global__ void k_sort() {
    __shared__ unsigned long long sk[NN];
    int b = blockIdx.x, t = threadIdx.x;
    float sval = g_score[b * NN + t];
    unsigned u = __float_as_uint(sval);
    u = (u & 0x80000000u) ? ~u : (u | 0x80000000u);
    u = ~u;
    unsigned long long key = ((unsigned long long)u << 32) | (unsigned)t;

    #pragma unroll
    for (int k = 2; k <= NN; k <<= 1) {
        #pragma unroll
        for (int j = k >> 1; j > 0; j >>= 1) {
            unsigned long long other;
            if (j >= 32) {
                __syncthreads();
                sk[t] = key;
                __syncthreads();
                other = sk[t ^ j];
            } else {
                other = __shfl_xor_sync(0xffffffffu, key, j);
            }
            bool takeMin = (((t & j) == 0) == ((t & k) == 0));
            bool less = key < other;
            key = (takeMin == less) ? key : other;
        }
    }

    int idx = (int)(key & 0xffffffffu);
    int gi  = b * NN + idx;
    g_order[b * NN + t] = idx;
    g_sr[b * NN + t]    = tanhf(g_score[gi]);
    g_dsrc[b * NN + t]  = g_ssrc[gi];
    g_ddst[b * NN + t]  = g_sdst[gi];
}

// -------- Kernel 3: banded window + per-segment exit/mask tail --------
__global__ void k_windows(const float* __restrict__ x,
                          const int*   __restrict__ ep) {
    __shared__ __align__(16) float tile[TROWS * NC];    // 24064 B
    __shared__ __align__(16) float sp4[TR * 15 * 4];    // 7680 B
    __shared__ __align__(16) float skk[TR * 15];        // 1920 B
    __shared__ __align__(16) float sddst[48];
    __shared__ int sjmp[TR];
    int b  = blockIdx.y;
    int r0 = blockIdx.x * TR;
    int t = threadIdx.x, w = t >> 5, lane = t & 31;
    const int* ord = g_order + b * NN;

    for (int rr = w; rr < TROWS; rr += 8) {
        int gr  = r0 + rr;
        int grc = gr < NN ? gr : (NN - 1);
        int id  = ord[grc];
        float4 v = *(const float4*)(x + ((size_t)(b * NN + id)) * NC + lane * 4);
        *(float4*)(tile + rr * NC + lane * 4) = v;
    }
    if (t < TROWS) {
        int gr  = r0 + t;
        int grc = gr < NN ? gr : (NN - 1);
        sddst[t] = g_ddst[b * NN + grc];
    }
    __syncthreads();

    // Phase A: warp w owns source rows rbase..rbase+3 in registers
    int rbase = w * 4;
    float4 xs0 = *(const float4*)(tile + (rbase + 0) * NC + lane * 4);
    float4 xs1 = *(const float4*)(tile + (rbase + 1) * NC + lane * 4);
    float4 xs2 = *(const float4*)(tile + (rbase + 2) * NC + lane * 4);
    float4 xs3 = *(const float4*)(tile + (rbase + 3) * NC + lane * 4);

    #pragma unroll
    for (int dd = 1; dd <= 18; dd++) {
        float4 xd = *(const float4*)(tile + (rbase + dd) * NC + lane * 4);
        #pragma unroll
        for (int i = 0; i < 4; i++) {
            int j = dd - i;
            if (j >= 1 && j <= 15) {
                float4 xs = (i == 0) ? xs0 : (i == 1) ? xs1 : (i == 2) ? xs2 : xs3;
                float dx = xs.x - xd.x, dy = xs.y - xd.y;
                float dz = xs.z - xd.z, dw = xs.w - xd.w;
                float p = dx*dx + dy*dy + dz*dz + dw*dw;
                p += __shfl_xor_sync(0xffffffffu, p, 16);
                p += __shfl_xor_sync(0xffffffffu, p, 8);
                p += __shfl_xor_sync(0xffffffffu, p, 4);
                if (lane < 4)
                    sp4[((rbase + i) * 15 + (j - 1)) * 4 + lane] = p;
            }
        }
    }
    __syncthreads();

    // Phase B1: sum 4 partials, kk = exp(-sqrt(d2)/2) - EPS
    for (int i = t; i < TR * 15; i += 256) {
        int rl = i / 15, jm1 = i - rl * 15;
        bool valid = (r0 + rl + jm1 + 1) < NN;
        float4 a = *(const float4*)(sp4 + i * 4);
        float d2 = (a.x + a.y) + (a.z + a.w);
        skk[i] = valid ? (expf(-0.5f * sqrtf(d2)) - 1e-20f) : -1e-20f;
    }
    __syncthreads();

    // Phase B2: thread-per-r softmax / max / argmax
    if (t < TR) {
        int r = r0 + t;
        if (r < NRES) {
            int epoch = *ep;
            float tau = (float)(10.0 * exp((double)epoch * -0.046051701859880914));
            float dsr = g_dsrc[b * NN + r];

            float att[16], kk[16];
            kk[0]  = 1.0f;
            att[0] = dsr + sddst[t];
            #pragma unroll
            for (int j = 1; j < NFS; j++) {
                bool valid = (r + j) < NN;
                kk[j]  = skk[t * 15 + (j - 1)];
                att[j] = valid ? (dsr + sddst[t + j]) : -1e9f;
            }
            float m = att[0];
            #pragma unroll
            for (int j = 1; j < NFS; j++) m = fmaxf(m, att[j]);
            float e[16], ssum = 0.0f;
            #pragma unroll
            for (int j = 0; j < NFS; j++) { e[j] = expf((att[j] - m) / tau); ssum += e[j]; }
            float inv = 1.0f / ssum;

            float wrow = -1e9f, best = -3e9f;
            int bj = 1;
            #pragma unroll
            for (int j = 0; j < NFS; j++) {
                bool valid = (r + j) < NN;
                float q  = kk[j] * (e[j] * inv);
                float qm = valid ? q : -1e9f;
                wrow = fmaxf(wrow, qm);
                if (j >= 1 && qm > best) { best = qm; bj = j; }
            }
            g_wv[b * NRES + r] = wrow * g_sr[b * NN + r];
            sjmp[t] = bj;
        }
    }
    __syncthreads();

    // Tail: per-position within-segment exit + visited mask (hidden latency)
    if (t < TR) {
        int r = r0 + t;
        if (r < NRES) {
            int e = r0 + TR; if (e > NRES) e = NRES;
            unsigned m = 0u;
            int p = r;
            while (p < e) { m |= 1u << (p - r0); p += sjmp[p - r0]; }
            g_exit[b * NN + r]  = p;
            g_maskf[b * NN + r] = m;
        }
    }
}

// -------- Kernel 4: short segment-hop + compacted pipelined gather --------
__global__ void k_chain(const float* __restrict__ x, float* __restrict__ out) {
    __shared__ float swv[NRES];
    __shared__ int   sord[NRES];
    __shared__ int   sexit[NRES];
    __shared__ unsigned smaskf[NRES];
    __shared__ int   sentry[16];
    __shared__ unsigned smask[16];
    __shared__ int   scnt[17];
    __shared__ int   sidx[NRES + 64];
    __shared__ float swt2[NRES + 64];
    __shared__ __align__(16) float part[16][NC];
    int b = blockIdx.x, t = threadIdx.x, w = t >> 5, lane = t & 31;  // 512 thr

    if (t < NRES) {
        swv[t]    = g_wv[b * NRES + t];
        sord[t]   = g_order[b * NN + t];
        sexit[t]  = g_exit[b * NN + t];
        smaskf[t] = g_maskf[b * NN + t];
    }
    if (t < 16) sentry[t] = -1;
    __syncthreads();

    // segment-to-segment hop: <=16 dependent LDS
    if (t == 0) {
        int p = 0;
        while (p < NRES) { sentry[p >> 5] = p; p = sexit[p]; }
    }
    __syncthreads();

    if (t < 16) {
        int e = sentry[t];
        unsigned m = (e >= 0) ? smaskf[e] : 0u;
        smask[t] = m;
        scnt[t]  = __popc(m);
    }
    __syncthreads();
    if (t == 0) {
        int a = 0;
        #pragma unroll
        for (int i = 0; i < 16; i++) { int c = scnt[i]; scnt[i] = a; a += c; }
        scnt[16] = a;
    }
    __syncthreads();

    // compaction (t<16) + padding (t in [64,128))
    if (t < 16) {
        unsigned m = smask[t];
        int o = scnt[t];
        while (m) {
            int bit = __ffs(m) - 1; m &= m - 1;
            int p = (t << 5) | bit;
            sidx[o] = sord[p];
            swt2[o] = swv[p];
            o++;
        }
    } else if (t >= 64 && t < 128) {
        int n = scnt[16], k = t - 64;
        sidx[n + k] = 0;
        swt2[n + k] = 0.0f;
    }
    __syncthreads();

    // pipelined gather: each warp takes chunks of 4 independent rows
    int n = scnt[16];
    const float* xb = x + (size_t)b * NN * NC;
    float ax = 0.f, ay = 0.f, az = 0.f, a4 = 0.f;
    for (int base = w * 4; base < n; base += 64) {
        float u0 = swt2[base + 0], u1 = swt2[base + 1];
        float u2 = swt2[base + 2], u3 = swt2[base + 3];
        float4 v0 = *(const float4*)(xb + (size_t)sidx[base + 0] * NC + lane * 4);
        float4 v1 = *(const float4*)(xb + (size_t)sidx[base + 1] * NC + lane * 4);
        float4 v2 = *(const float4*)(xb + (size_t)sidx[base + 2] * NC + lane * 4);
        float4 v3 = *(const float4*)(xb + (size_t)sidx[base + 3] * NC + lane * 4);
        ax += u0*v0.x + u1*v1.x + u2*v2.x + u3*v3.x;
        ay += u0*v0.y + u1*v1.y + u2*v2.y + u3*v3.y;
        az += u0*v0.z + u1*v1.z + u2*v2.z + u3*v3.z;
        a4 += u0*v0.w + u1*v1.w + u2*v2.w + u3*v3.w;
    }
    part[w][lane * 4 + 0] = ax;
    part[w][lane * 4 + 1] = ay;
    part[w][lane * 4 + 2] = az;
    part[w][lane * 4 + 3] = a4;
    __syncthreads();

    if (t < NC) {
        float s = 0.0f;
        #pragma unroll
        for (int w2 = 0; w2 < 16; w2++) s += part[w2][t];
        out[b * NC + t] = s;
    }
}

extern "C" void kernel_launch(void* const* d_in, const int* in_sizes, int n_in,
                              void* d_out, int out_size) {
    const float* x   = (const float*)d_in[0];
    // d_in[1] = edge_index (unused by the reference forward pass)
    const float* sw  = (const float*)d_in[2];
    const float* ap  = (const float*)d_in[3];
    const int*   ep  = (const int*)d_in[4];
    float* out = (float*)d_out;

    k_scores<<<NBN / 8, 256>>>(x, sw, ap);
    k_sort<<<NB, NN>>>();
    dim3 gw((NRES + TR - 1) / TR, NB);
    k_windows<<<gw, 256>>>(x, ep);
    k_chain<<<NB, 512>>>(x, out);
}

// round 10
// speedup vs baseline: 1.4679x; 1.0008x over previous
#include <cuda_runtime.h>
#include <math.h>

#define NB   64
#define NN   512
#define NC   128
#define NFS  16
#define NRES 511
#define NBN  (NB*NN)
#define TR   32
#define TROWS (TR + NFS - 1)   // 47 tile rows

// Scratch (no allocations allowed)
__device__ float g_score[NBN];
__device__ float g_ssrc[NBN];
__device__ float g_sdst[NBN];
__device__ float g_nx[NBN];          // |x|^2 per node
__device__ int   g_order[NBN];
__device__ float g_sr[NBN];
__device__ float g_dsrc[NBN];
__device__ float g_ddst[NBN];
__device__ float g_wv[NB*NRES];
__device__ int   g_exit[NBN];        // exit position from every start p
__device__ unsigned g_maskf[NBN];    // visited-bits within segment from p

// -------- Kernel 1: per-node score + attention dots + |x|^2 --------
__global__ void k_scores(const float* __restrict__ x,
                         const float* __restrict__ sw,
                         const float* __restrict__ ap) {
    __shared__ float sp[8][5][8];
    __shared__ float sfin[8][5];
    int t = threadIdx.x, w = t >> 5, lane = t & 31;
    int node = blockIdx.x * 8 + w;

    float4 xv = *(const float4*)(x  + (size_t)node * NC + lane * 4);
    float4 wv = *(const float4*)(sw + lane * 4);
    float4 as = *(const float4*)(ap + lane * 4);
    float4 ad = *(const float4*)(ap + NC + lane * 4);
    float s  = xv.x*wv.x + xv.y*wv.y + xv.z*wv.z + xv.w*wv.w;
    float ps = xv.x*as.x + xv.y*as.y + xv.z*as.z + xv.w*as.w;
    float pd = xv.x*ad.x + xv.y*ad.y + xv.z*ad.z + xv.w*ad.w;
    float wn = wv.x*wv.x + wv.y*wv.y + wv.z*wv.z + wv.w*wv.w;
    float nx = xv.x*xv.x + xv.y*xv.y + xv.z*xv.z + xv.w*xv.w;
    #pragma unroll
    for (int o = 16; o >= 8; o >>= 1) {
        s  += __shfl_xor_sync(0xffffffffu, s,  o);
        ps += __shfl_xor_sync(0xffffffffu, ps, o);
        pd += __shfl_xor_sync(0xffffffffu, pd, o);
        wn += __shfl_xor_sync(0xffffffffu, wn, o);
        nx += __shfl_xor_sync(0xffffffffu, nx, o);
    }
    if (lane < 8) {
        sp[w][0][lane] = s;  sp[w][1][lane] = ps;
        sp[w][2][lane] = pd; sp[w][3][lane] = wn;
        sp[w][4][lane] = nx;
    }
    __syncthreads();
    if (t < 40) {
        int nd = t / 5, v = t - nd * 5;
        const float* q = sp[nd][v];
        sfin[nd][v] = ((q[0]+q[1])+(q[2]+q[3])) + ((q[4]+q[5])+(q[6]+q[7]));
    }
    __syncthreads();
    if (t < 8) {
        int gn = blockIdx.x * 8 + t;
        g_score[gn] = sfin[t][0] / sqrtf(sfin[t][3]);
        g_ssrc[gn]  = sfin[t][1];
        g_sdst[gn]  = sfin[t][2];
        g_nx[gn]    = sfin[t][4];
    }
}

// -------- Kernel 2: register-resident bitonic sort with u64 keys --------
__global__ void k_sort() {
    __shared__ unsigned long long sk[NN];
    int b = blockIdx.x, t = threadIdx.x;
    float sval = g_score[b * NN + t];
    unsigned u = __float_as_uint(sval);
    u = (u & 0x80000000u) ? ~u : (u | 0x80000000u);
    u = ~u;
    unsigned long long key = ((unsigned long long)u << 32) | (unsigned)t;

    #pragma unroll
    for (int k = 2; k <= NN; k <<= 1) {
        #pragma unroll
        for (int j = k >> 1; j > 0; j >>= 1) {
            unsigned long long other;
            if (j >= 32) {
                __syncthreads();
                sk[t] = key;
                __syncthreads();
                other = sk[t ^ j];
            } else {
                other = __shfl_xor_sync(0xffffffffu, key, j);
            }
            bool takeMin = (((t & j) == 0) == ((t & k) == 0));
            bool less = key < other;
            key = (takeMin == less) ? key : other;
        }
    }

    int idx = (int)(key & 0xffffffffu);
    int gi  = b * NN + idx;
    g_order[b * NN + t] = idx;
    g_sr[b * NN + t]    = tanhf(g_score[gi]);
    g_dsrc[b * NN + t]  = g_ssrc[gi];
    g_ddst[b * NN + t]  = g_sdst[gi];
}

// -------- Kernel 3: banded window via dot identity + exit/mask tail --------
__global__ void k_windows(const float* __restrict__ x,
                          const int*   __restrict__ ep) {
    __shared__ __align__(16) float tile[TROWS * NC];    // 24064 B
    __shared__ __align__(16) float sp8[TR * 15 * 8];    // 15360 B
    __shared__ __align__(16) float skk[TR * 15];        // 1920 B
    __shared__ __align__(16) float sddst[48];
    __shared__ __align__(16) float snx[48];
    __shared__ int sjmp[TR];
    int b  = blockIdx.y;
    int r0 = blockIdx.x * TR;
    int t = threadIdx.x, w = t >> 5, lane = t & 31;
    const int* ord = g_order + b * NN;

    for (int rr = w; rr < TROWS; rr += 8) {
        int gr  = r0 + rr;
        int grc = gr < NN ? gr : (NN - 1);
        int id  = ord[grc];
        float4 v = *(const float4*)(x + ((size_t)(b * NN + id)) * NC + lane * 4);
        *(float4*)(tile + rr * NC + lane * 4) = v;
    }
    if (t < TROWS) {
        int gr  = r0 + t;
        int grc = gr < NN ? gr : (NN - 1);
        sddst[t] = g_ddst[b * NN + grc];
        snx[t]   = g_nx[b * NN + ord[grc]];
    }
    __syncthreads();

    // Phase A: dot products only (identity form), warp w owns 4 source rows
    int rbase = w * 4;
    float4 xs0 = *(const float4*)(tile + (rbase + 0) * NC + lane * 4);
    float4 xs1 = *(const float4*)(tile + (rbase + 1) * NC + lane * 4);
    float4 xs2 = *(const float4*)(tile + (rbase + 2) * NC + lane * 4);
    float4 xs3 = *(const float4*)(tile + (rbase + 3) * NC + lane * 4);

    #pragma unroll
    for (int dd = 1; dd <= 18; dd++) {
        float4 xd = *(const float4*)(tile + (rbase + dd) * NC + lane * 4);
        #pragma unroll
        for (int i = 0; i < 4; i++) {
            int j = dd - i;
            if (j >= 1 && j <= 15) {
                float4 xs = (i == 0) ? xs0 : (i == 1) ? xs1 : (i == 2) ? xs2 : xs3;
                float p = xs.x*xd.x + xs.y*xd.y + xs.z*xd.z + xs.w*xd.w;
                p += __shfl_xor_sync(0xffffffffu, p, 16);
                p += __shfl_xor_sync(0xffffffffu, p, 8);
                if (lane < 8)
                    sp8[((rbase + i) * 15 + (j - 1)) * 8 + lane] = p;
            }
        }
    }
    __syncthreads();

    // Phase B1: d2 = nx_s + nx_d - 2*dot ; kk = exp(-sqrt(d2)/2) - EPS
    for (int i = t; i < TR * 15; i += 256) {
        int rl = i / 15, jm1 = i - rl * 15;
        bool valid = (r0 + rl + jm1 + 1) < NN;
        float4 a  = *(const float4*)(sp8 + i * 8);
        float4 b4 = *(const float4*)(sp8 + i * 8 + 4);
        float dot = ((a.x + a.y) + (a.z + a.w)) + ((b4.x + b4.y) + (b4.z + b4.w));
        float d2 = fmaxf(snx[rl] + snx[rl + jm1 + 1] - 2.0f * dot, 0.0f);
        skk[i] = valid ? (expf(-0.5f * sqrtf(d2)) - 1e-20f) : -1e-20f;
    }
    __syncthreads();

    // Phase B2: thread-per-r softmax / max / argmax
    if (t < TR) {
        int r = r0 + t;
        if (r < NRES) {
            int epoch = *ep;
            float tau = (float)(10.0 * exp((double)epoch * -0.046051701859880914));
            float dsr = g_dsrc[b * NN + r];

            float att[16], kk[16];
            kk[0]  = 1.0f;
            att[0] = dsr + sddst[t];
            #pragma unroll
            for (int j = 1; j < NFS; j++) {
                bool valid = (r + j) < NN;
                kk[j]  = skk[t * 15 + (j - 1)];
                att[j] = valid ? (dsr + sddst[t + j]) : -1e9f;
            }
            float m = att[0];
            #pragma unroll
            for (int j = 1; j < NFS; j++) m = fmaxf(m, att[j]);
            float e[16], ssum = 0.0f;
            #pragma unroll
            for (int j = 0; j < NFS; j++) { e[j] = expf((att[j] - m) / tau); ssum += e[j]; }
            float inv = 1.0f / ssum;

            float wrow = -1e9f, best = -3e9f;
            int bj = 1;
            #pragma unroll
            for (int j = 0; j < NFS; j++) {
                bool valid = (r + j) < NN;
                float q  = kk[j] * (e[j] * inv);
                float qm = valid ? q : -1e9f;
                wrow = fmaxf(wrow, qm);
                if (j >= 1 && qm > best) { best = qm; bj = j; }
            }
            g_wv[b * NRES + r] = wrow * g_sr[b * NN + r];
            sjmp[t] = bj;
        }
    }
    __syncthreads();

    // Tail: per-position within-segment exit + visited mask
    if (t < TR) {
        int r = r0 + t;
        if (r < NRES) {
            int e = r0 + TR; if (e > NRES) e = NRES;
            unsigned m = 0u;
            int p = r;
            while (p < e) { m |= 1u << (p - r0); p += sjmp[p - r0]; }
            g_exit[b * NN + r]  = p;
            g_maskf[b * NN + r] = m;
        }
    }
}

// -------- Kernel 4: channel-split chain, 4 CTAs per batch --------
__global__ void k_chain(const float* __restrict__ x, float* __restrict__ out) {
    __shared__ float swv[NRES];
    __shared__ int   sord[NRES];
    __shared__ int   sexit[NRES];
    __shared__ unsigned smaskf[NRES];
    __shared__ int   sentry[16];
    __shared__ unsigned smask[16];
    __shared__ int   scnt[17];
    __shared__ int   sidx[NRES + 16];
    __shared__ float swt2[NRES + 16];
    __shared__ float part[4][32];
    int b = blockIdx.x >> 2, q = blockIdx.x & 3;   // batch, channel quarter
    int t = threadIdx.x, w = t >> 5, lane = t & 31;  // 128 threads

    for (int i = t; i < NRES; i += 128) {
        swv[i]    = g_wv[b * NRES + i];
        sord[i]   = g_order[b * NN + i];
        sexit[i]  = g_exit[b * NN + i];
        smaskf[i] = g_maskf[b * NN + i];
    }
    if (t < 16) sentry[t] = -1;
    __syncthreads();

    // segment-to-segment hop: <=16 dependent LDS
    if (t == 0) {
        int p = 0;
        while (p < NRES) { sentry[p >> 5] = p; p = sexit[p]; }
    }
    __syncthreads();

    if (t < 16) {
        int e = sentry[t];
        unsigned m = (e >= 0) ? smaskf[e] : 0u;
        smask[t] = m;
        scnt[t]  = __popc(m);
    }
    __syncthreads();
    if (t == 0) {
        int a = 0;
        #pragma unroll
        for (int i = 0; i < 16; i++) { int c = scnt[i]; scnt[i] = a; a += c; }
        scnt[16] = a;
    }
    __syncthreads();

    // compaction (t<16) + zero-padding (t in [32,48))
    if (t < 16) {
        unsigned m = smask[t];
        int o = scnt[t];
        while (m) {
            int bit = __ffs(m) - 1; m &= m - 1;
            int p = (t << 5) | bit;
            sidx[o] = sord[p];
            swt2[o] = swv[p];
            o++;
        }
    } else if (t >= 32 && t < 48) {
        int n = scnt[16], k = t - 32;
        sidx[n + k] = 0;
        swt2[n + k] = 0.0f;
    }
    __syncthreads();

    // gather: 4 warps x chunks of 4 independent rows; lane = 1 channel
    int n = scnt[16];
    const float* xb = x + (size_t)b * NN * NC + q * 32 + lane;
    float acc = 0.0f;
    for (int base = w * 4; base < n; base += 16) {
        float u0 = swt2[base + 0], u1 = swt2[base + 1];
        float u2 = swt2[base + 2], u3 = swt2[base + 3];
        float v0 = xb[(size_t)sidx[base + 0] * NC];
        float v1 = xb[(size_t)sidx[base + 1] * NC];
        float v2 = xb[(size_t)sidx[base + 2] * NC];
        float v3 = xb[(size_t)sidx[base + 3] * NC];
        acc += u0*v0 + u1*v1 + u2*v2 + u3*v3;
    }
    part[w][lane] = acc;
    __syncthreads();

    if (t < 32)
        out[b * NC + q * 32 + t] =
            (part[0][t] + part[1][t]) + (part[2][t] + part[3][t]);
}

extern "C" void kernel_launch(void* const* d_in, const int* in_sizes, int n_in,
                              void* d_out, int out_size) {
    const float* x   = (const float*)d_in[0];
    // d_in[1] = edge_index (unused by the reference forward pass)
    const float* sw  = (const float*)d_in[2];
    const float* ap  = (const float*)d_in[3];
    const int*   ep  = (const int*)d_in[4];
    float* out = (float*)d_out;

    k_scores<<<NBN / 8, 256>>>(x, sw, ap);
    k_sort<<<NB, NN>>>();
    dim3 gw((NRES + TR - 1) / TR, NB);
    k_windows<<<gw, 256>>>(x, ep);
    k_chain<<<NB * 4, 128>>>(x, out);
}